// round 15
// baseline (speedup 1.0000x reference)
#include <cuda_runtime.h>
#include <cuda_fp16.h>

#define DOUT 128
#define EDIM 16
#define MAX_NODES 100000
#define MAX_EDGES 800000
#define CAP 64
#define FULL 0xffffffffu

typedef unsigned long long u64;

// Scratch (device globals — no allocations allowed)
__device__ __half g_xwh[(size_t)MAX_NODES * DOUT];  // 25.6 MB, L2-resident
__device__ __half g_mh[(size_t)MAX_EDGES * DOUT];   // 204.8 MB, modulated messages
__device__ int    g_cnt[MAX_NODES];
__device__ int2   g_elist[(size_t)MAX_NODES * CAP]; // (src, edge_id) buckets

// Packed fp32x2 ops (ptxas never auto-emits these from C++).
__device__ __forceinline__ u64 ffma2(u64 a, u64 b, u64 c) {
    u64 d;
    asm("fma.rn.f32x2 %0, %1, %2, %3;" : "=l"(d) : "l"(a), "l"(b), "l"(c));
    return d;
}
__device__ __forceinline__ u64 splat2(float v) {
    u64 d;
    asm("mov.b64 %0, {%1, %1};" : "=l"(d) : "f"(v));
    return d;
}
__device__ __forceinline__ u64 pack2(float lo, float hi) {
    u64 d;
    asm("mov.b64 %0, {%1, %2};" : "=l"(d) : "f"(lo), "f"(hi));
    return d;
}

// L2 eviction policies via createpolicy + cache_hint.
__device__ __forceinline__ u64 policy_evict_last() {
    u64 p;
    asm("createpolicy.fractional.L2::evict_last.b64 %0, 1.0;" : "=l"(p));
    return p;
}
__device__ __forceinline__ u64 policy_evict_first() {
    u64 p;
    asm("createpolicy.fractional.L2::evict_first.b64 %0, 1.0;" : "=l"(p));
    return p;
}
// 8-byte half4 load with policy.
__device__ __forceinline__ uint2 ldg_h4(const __half* p, u64 pol) {
    uint2 v;
    asm volatile("ld.global.nc.L2::cache_hint.v2.b32 {%0, %1}, [%2], %3;"
                 : "=r"(v.x), "=r"(v.y) : "l"(p), "l"(pol));
    return v;
}
__device__ __forceinline__ void h4_to_f32x2(uint2 h, u64& lo, u64& hi) {
    float2 f01 = __half22float2(*reinterpret_cast<__half2*>(&h.x));
    float2 f23 = __half22float2(*reinterpret_cast<__half2*>(&h.y));
    lo = pack2(f01.x, f01.y);
    hi = pack2(f23.x, f23.y);
}
__device__ __forceinline__ float4 ldg_f4(const float4* p, u64 pol) {
    float4 v;
    asm volatile("ld.global.nc.L2::cache_hint.v4.f32 {%0, %1, %2, %3}, [%4], %5;"
                 : "=f"(v.x), "=f"(v.y), "=f"(v.z), "=f"(v.w) : "l"(p), "l"(pol));
    return v;
}
__device__ __forceinline__ void st_out(float* p, u64 pol, u64 lo, u64 hi) {
    asm volatile("st.global.L2::cache_hint.v2.b64 [%0], {%1, %2}, %3;"
                 :: "l"(p), "l"(lo), "l"(hi), "l"(pol));
}
__device__ __forceinline__ void pf_l2(const void* p) {
    asm volatile("prefetch.global.L2 [%0];" :: "l"(p));
}

__global__ void zero_cnt_kernel(int n) {
    int i = blockIdx.x * blockDim.x + threadIdx.x;
    if (i < n) g_cnt[i] = 0;
}

// xw = x @ W (fp16 out). 64 rows/block, thread = 8 rows x 4 cols, f32x2 math.
__global__ __launch_bounds__(256)
void gemm_xw_kernel(const float* __restrict__ x, const float* __restrict__ W, int n) {
    __shared__ float Ws[DOUT][DOUT];
    __shared__ float xs[64][DOUT];
    int tid = threadIdx.x;

    const float4* W4 = (const float4*)W;
    float4* Ws4 = (float4*)Ws;
    #pragma unroll
    for (int i = 0; i < 16; i++) Ws4[tid + i * 256] = W4[tid + i * 256];

    int row0 = blockIdx.x * 64;
    const float4* x4 = (const float4*)(x + (size_t)row0 * DOUT);
    float4* xs4 = (float4*)xs;
    #pragma unroll
    for (int i = 0; i < 8; i++) {
        int idx = tid + i * 256;
        int grow = row0 + (idx >> 5);
        if (grow < n) xs4[idx] = x4[idx];
    }
    __syncthreads();

    int rg = tid >> 5;
    int cg = tid & 31;

    u64 acc[8][2];
    #pragma unroll
    for (int r = 0; r < 8; r++) { acc[r][0] = 0ULL; acc[r][1] = 0ULL; }

    #pragma unroll 4
    for (int k = 0; k < DOUT; k += 2) {
        const u64* wa = (const u64*)&Ws[k][cg * 4];
        const u64* wb = (const u64*)&Ws[k + 1][cg * 4];
        u64 wa0 = wa[0], wa1 = wa[1];
        u64 wb0 = wb[0], wb1 = wb[1];
        #pragma unroll
        for (int r = 0; r < 8; r++) {
            float2 xp = *(const float2*)&xs[rg * 8 + r][k];
            u64 xk0 = splat2(xp.x);
            u64 xk1 = splat2(xp.y);
            acc[r][0] = ffma2(xk0, wa0, acc[r][0]);
            acc[r][1] = ffma2(xk0, wa1, acc[r][1]);
            acc[r][0] = ffma2(xk1, wb0, acc[r][0]);
            acc[r][1] = ffma2(xk1, wb1, acc[r][1]);
        }
    }

    #pragma unroll
    for (int r = 0; r < 8; r++) {
        int grow = row0 + rg * 8 + r;
        if (grow < n) {
            float a0, a1, a2, a3;
            asm("mov.b64 {%0, %1}, %2;" : "=f"(a0), "=f"(a1) : "l"(acc[r][0]));
            asm("mov.b64 {%0, %1}, %2;" : "=f"(a2), "=f"(a3) : "l"(acc[r][1]));
            __half2 h01 = __floats2half2_rn(a0, a1);
            __half2 h23 = __floats2half2_rn(a2, a3);
            uint2 st;
            st.x = *reinterpret_cast<unsigned*>(&h01);
            st.y = *reinterpret_cast<unsigned*>(&h23);
            *(uint2*)&g_xwh[(size_t)grow * DOUT + cg * 4] = st;
        }
    }
}

// One thread per edge: append (src, e) to dst's bucket. Int atomics only.
__global__ __launch_bounds__(256)
void scatter_kernel(const int* __restrict__ ei, int nE) {
    int e = blockIdx.x * blockDim.x + threadIdx.x;
    if (e >= nE) return;
    int src = ei[e];
    int dst = ei[nE + e];
    int slot = atomicAdd(&g_cnt[dst], 1);
    if (slot < CAP)
        g_elist[(size_t)dst * CAP + slot] = make_int2(src, e);
}

// M[e] = ea[e] @ edge_w (fp16 out). Edge-ordered: uniform loads, coalesced
// stores, no gather chains -> pipelines freely. Warp owns edges, lane owns
// 4 output cols (weights in 64 regs, loaded once).
__global__ __launch_bounds__(256, 2)
void modulate_kernel(const float* __restrict__ ea,
                     const float* __restrict__ ew, int nE) {
    int lane = threadIdx.x & 31;
    int gw = (blockIdx.x * blockDim.x + threadIdx.x) >> 5;
    int nw = (gridDim.x * blockDim.x) >> 5;

    u64 wp[EDIM][2];
    #pragma unroll
    for (int k = 0; k < EDIM; k++) {
        const u64* w = (const u64*)&ew[k * DOUT + lane * 4];
        wp[k][0] = w[0];
        wp[k][1] = w[1];
    }

    for (int e = gw; e < nE; e += nw) {
        const float4* ep = (const float4*)&ea[(size_t)e * EDIM];
        float4 A0 = __ldg(&ep[0]);
        float4 A1 = __ldg(&ep[1]);
        float4 A2 = __ldg(&ep[2]);
        float4 A3 = __ldg(&ep[3]);

        float a[16] = {A0.x, A0.y, A0.z, A0.w, A1.x, A1.y, A1.z, A1.w,
                       A2.x, A2.y, A2.z, A2.w, A3.x, A3.y, A3.z, A3.w};
        u64 c0 = 0, c1 = 0;
        #pragma unroll
        for (int k = 0; k < EDIM; k++) {
            u64 s = splat2(a[k]);
            c0 = ffma2(s, wp[k][0], c0);
            c1 = ffma2(s, wp[k][1], c1);
        }

        float f0, f1, f2, f3;
        asm("mov.b64 {%0, %1}, %2;" : "=f"(f0), "=f"(f1) : "l"(c0));
        asm("mov.b64 {%0, %1}, %2;" : "=f"(f2), "=f"(f3) : "l"(c1));
        __half2 h01 = __floats2half2_rn(f0, f1);
        __half2 h23 = __floats2half2_rn(f2, f3);
        uint2 st;
        st.x = *reinterpret_cast<unsigned*>(&h01);
        st.y = *reinterpret_cast<unsigned*>(&h23);
        *(uint2*)&g_mh[(size_t)e * DOUT + lane * 4] = st;   // coalesced 256B
    }
}

// PERSISTENT warps, 1 warp/node. Tiny per-edge body: LDG.64 M[e] + LDG.64
// xwh[src] + 2 ffma2. Low regs -> high occupancy hides the gather latency.
__global__ __launch_bounds__(256, 5)
void aggregate_kernel(const float* __restrict__ b,
                      float* __restrict__ out, int n) {
    int lane = threadIdx.x & 31;
    int gw = (blockIdx.x * blockDim.x + threadIdx.x) >> 5;
    int nw = (gridDim.x * blockDim.x) >> 5;

    u64 pol_keep = policy_evict_last();
    u64 pol_stream = policy_evict_first();

    const u64* b2 = (const u64*)&b[lane * 4];
    u64 bias0 = b2[0], bias1 = b2[1];

    for (int v = gw; v < n; v += nw) {
        int deg = g_cnt[v];
        if (deg > CAP) deg = CAP;

        u64 acc0 = bias0, acc1 = bias1;

        if (deg > 0) {
            const int2* bucket = &g_elist[(size_t)v * CAP];

            int4 se_c = *(const int4*)&bucket[0];
            if (deg < 2) { se_c.z = se_c.x; se_c.w = se_c.y; }

            // Loads for pair 0.
            uint2 x0 = ldg_h4(&g_xwh[(size_t)se_c.x * DOUT + lane * 4], pol_keep);
            uint2 m0 = ldg_h4(&g_mh[(size_t)se_c.y * DOUT + lane * 4], pol_stream);
            uint2 x1 = ldg_h4(&g_xwh[(size_t)se_c.z * DOUT + lane * 4], pol_keep);
            uint2 m1 = ldg_h4(&g_mh[(size_t)se_c.w * DOUT + lane * 4], pol_stream);

            for (int j = 0; j < deg; j += 2) {
                bool v1 = (j + 1 < deg);

                // Prefetch + load pair j+2 (registers double-buffered).
                bool hn0 = (j + 2 < deg);
                int jn = hn0 ? (j + 2) : 0;
                int4 se_n = *(const int4*)&bucket[jn];
                if (j + 3 >= deg) { se_n.z = se_n.x; se_n.w = se_n.y; }
                uint2 xn0 = ldg_h4(&g_xwh[(size_t)se_n.x * DOUT + lane * 4], pol_keep);
                uint2 mn0 = ldg_h4(&g_mh[(size_t)se_n.y * DOUT + lane * 4], pol_stream);
                uint2 xn1 = ldg_h4(&g_xwh[(size_t)se_n.z * DOUT + lane * 4], pol_keep);
                uint2 mn1 = ldg_h4(&g_mh[(size_t)se_n.w * DOUT + lane * 4], pol_stream);

                // Math for pair j.
                u64 xv0, xv1, mv0, mv1;
                h4_to_f32x2(x0, xv0, xv1);
                h4_to_f32x2(m0, mv0, mv1);
                acc0 = ffma2(mv0, xv0, acc0);
                acc1 = ffma2(mv1, xv1, acc1);

                if (v1) {
                    u64 yv0, yv1, nv0, nv1;
                    h4_to_f32x2(x1, yv0, yv1);
                    h4_to_f32x2(m1, nv0, nv1);
                    acc0 = ffma2(nv0, yv0, acc0);
                    acc1 = ffma2(nv1, yv1, acc1);
                }

                x0 = xn0; m0 = mn0; x1 = xn1; m1 = mn1;
            }
        }

        st_out(&out[(size_t)v * DOUT + lane * 4], pol_stream, acc0, acc1);
    }
}

extern "C" void kernel_launch(void* const* d_in, const int* in_sizes, int n_in,
                              void* d_out, int out_size) {
    const float* x  = (const float*)d_in[0];
    const int*   ei = (const int*)d_in[1];
    const float* ea = (const float*)d_in[2];
    const float* W  = (const float*)d_in[3];
    const float* ew = (const float*)d_in[4];
    const float* b  = (const float*)d_in[5];
    float* out = (float*)d_out;

    int n  = in_sizes[0] / DOUT;   // 100000 nodes
    int nE = in_sizes[1] / 2;      // 800000 edges

    zero_cnt_kernel<<<(n + 255) / 256, 256>>>(n);
    gemm_xw_kernel<<<(n + 63) / 64, 256>>>(x, W, n);
    scatter_kernel<<<(nE + 255) / 256, 256>>>(ei, nE);
    modulate_kernel<<<592, 256>>>(ea, ew, nE);
    aggregate_kernel<<<740, 256>>>(b, out, n);
}